// round 7
// baseline (speedup 1.0000x reference)
#include <cuda_runtime.h>
#include <cuda_fp16.h>
#include <cstdint>

#define NMAX 80000
#define DD   64

__device__ __align__(16) __half g_xt_h[NMAX * DD];   // tangent feats (fp16)
__device__ __align__(16) float  g_agg [NMAX * DD];   // segment-sum accumulator
__device__ float g_hb1[DD + 2];
__device__ float g_hb2[DD + 2];

// ---------------------------------------------------------------------------
__device__ __forceinline__ float warpSum(float v) {
#pragma unroll
    for (int o = 16; o; o >>= 1) v += __shfl_xor_sync(0xffffffffu, v, o);
    return v;
}

// fast tanh for x >= 0: 1 - 2/(e^{2x}+1). Safe at x->0 and x->inf.
__device__ __forceinline__ float tanh_fast(float x) {
    float e = __expf(2.0f * x);
    return 1.0f - 2.0f * __fdividef(1.0f, e + 1.0f);
}

__device__ __forceinline__ float artanh_fast(float x) {
    x = fminf(fmaxf(x, -1.0f + 1e-7f), 1.0f - 1e-7f);
    return 0.5f * __logf(__fdividef(1.0f + x, 1.0f - x));
}

template<int U>
__device__ __forceinline__ void butterflyN(float* s) {
#pragma unroll
    for (int o = 16; o; o >>= 1) {
#pragma unroll
        for (int u = 0; u < U; u++) s[u] += __shfl_xor_sync(0xffffffffu, s[u], o);
    }
}
template<int U>
__device__ __forceinline__ void butterflyNx2(float* s1, float* s2) {
#pragma unroll
    for (int o = 16; o; o >>= 1) {
#pragma unroll
        for (int u = 0; u < U; u++) {
            s1[u] += __shfl_xor_sync(0xffffffffu, s1[u], o);
            s2[u] += __shfl_xor_sync(0xffffffffu, s2[u], o);
        }
    }
}

// ---------------------------------------------------------------------------
__global__ void k_hb(const float* __restrict__ b1, const float* __restrict__ b2) {
    int w = threadIdx.x >> 5, lane = threadIdx.x & 31;
    const float* b = w ? b2 : b1;
    float* out = w ? g_hb2 : g_hb1;
    float v0 = b[lane], v1 = b[lane + 32];
    float ss = warpSum(v0 * v0 + v1 * v1);
    float nb = fmaxf(sqrtf(ss), 1e-15f);
    float fac = fminf(tanh_fast(nb), 0.996f) / nb;
    float h0 = fac * v0, h1 = fac * v1;
    out[lane] = h0; out[lane + 32] = h1;
    float ss2 = warpSum(h0 * h0 + h1 * h1);
    if (lane == 0) out[64] = ss2;
}

// ---------------------------------------------------------------------------
// HypLinear epilogue for U nodes, interleaved; 2 butterflies; analytic
// mobius_add output norm (no 3rd reduction).
template<int U>
__device__ __forceinline__ void epilogueN(const float* mx0, const float* mx1,
                                          const float* xn,
                                          const float* __restrict__ hb,
                                          int lane, int nbase, int N,
                                          __half* __restrict__ outbase) {
    float hb0 = hb[lane], hb1v = hb[lane + 32], y2 = hb[64];
    float s1[U], s2[U];
#pragma unroll
    for (int u = 0; u < U; u++) {
        s1[u] = mx0[u] * mx0[u] + mx1[u] * mx1[u];
        s2[u] = mx0[u] * hb0 + mx1[u] * hb1v;
    }
    butterflyNx2<U>(s1, s2);
#pragma unroll
    for (int u = 0; u < U; u++) {
        float m2 = s1[u];
        float mxn_raw = sqrtf(m2);
        float mxn = fmaxf(mxn_raw, 1e-15f);
        float t = tanh_fast(__fdividef(mxn, xn[u]) * artanh_fast(xn[u]));
        float r = __fdividef(t, mxn);
        float nmv = t * __fdividef(mxn_raw, mxn);
        float nmvc = fmaxf(nmv, 1e-15f);
        float s = (nmvc > 0.996f) ? __fdividef(0.996f, nmvc) : 1.0f;
        float g = r * s;                     // mv = g * mx
        float nm = nmv * s;
        float x2 = nm * nm;
        float xy = g * s2[u];
        float ca = 1.0f + 2.0f * xy + y2;
        float cb = 1.0f - x2;
        float den = fmaxf(1.0f + 2.0f * xy + x2 * y2, 1e-15f);
        float inv = __fdividef(1.0f, den);
        float n2 = (ca * ca * x2 + 2.0f * ca * cb * xy + cb * cb * y2) * inv * inv;
        float nh = fmaxf(sqrtf(n2), 1e-15f);
        float sc = (nh > 0.996f) ? __fdividef(0.996f, nh) : 1.0f;
        float nhp = fmaxf(fminf(nh, 0.996f), 1e-15f);
        float lf = __fdividef(artanh_fast(nhp), nhp);
        float fac = lf * sc * inv;
        float h0 = fac * (ca * g * mx0[u] + cb * hb0);
        float h1 = fac * (ca * g * mx1[u] + cb * hb1v);
        if (nbase + u < N) {
            __half* out = outbase + (size_t)(nbase + u) * 64;
            out[lane]      = __float2half_rn(h0);
            out[lane + 32] = __float2half_rn(h1);
        }
    }
}

// ---------------------------------------------------------------------------
// agg -> h (HypAgg tail + HypAct) for U nodes, interleaved butterflies.
template<int U>
__device__ __forceinline__ void agg_to_hN(const float* a0, const float* a1,
                                          float* h0, float* h1, float* xn) {
    float s[U];
#pragma unroll
    for (int u = 0; u < U; u++) s[u] = a0[u] * a0[u] + a1[u] * a1[u];
    butterflyN<U>(s);
    float u0[U], u1[U];
#pragma unroll
    for (int u = 0; u < U; u++) {
        float na = fmaxf(sqrtf(s[u]), 1e-15f);
        float t = tanh_fast(na);
        float tc = fminf(t, 0.996f);
        float hfac = __fdividef(tc, na);
        float hn = fmaxf(tc, 1e-15f);
        float vf = __fdividef(artanh_fast(hn), hn) * hfac;
        u0[u] = fmaxf(vf * a0[u], 0.f);
        u1[u] = fmaxf(vf * a1[u], 0.f);
        s[u] = u0[u] * u0[u] + u1[u] * u1[u];
    }
    butterflyN<U>(s);
#pragma unroll
    for (int u = 0; u < U; u++) {
        float nu = fmaxf(sqrtf(s[u]), 1e-15f);
        float tu = tanh_fast(nu);
        float tcu = fminf(tu, 0.996f);
        float f2 = __fdividef(tcu, nu);
        h0[u] = f2 * u0[u];
        h1[u] = f2 * u1[u];
        xn[u] = fmaxf(tcu, 1e-15f);
    }
}

// ---------------------------------------------------------------------------
// Layer 1: encode + GEMM (K=256) + epilogue.
// 128 thr = 4 warps; 2 passes x 8 nodes per warp = 64 nodes/block.
// W1 in padded smem [64][65] f4; per-pass x stage 32 nodes x 64 f4 (32KB).
// smem = 66.5K + 32K = 98.5KB -> 2 blocks/SM. Zeroes g_agg rows.
#define L1_NT   128
#define L1_UP   8
#define L1_NB   64
#define L1_WS   (64 * 65)
__global__ void __launch_bounds__(L1_NT)
k_lin1(const float4* __restrict__ x, const float4* __restrict__ W1, int N) {
    extern __shared__ float4 smem[];
    float4* ws = smem;                 // [64][65]
    float4* xs = smem + L1_WS;         // [32 nodes][64]

    int tid  = threadIdx.x;
    int lane = tid & 31;
    int wib  = tid >> 5;
    int blockbase = blockIdx.x * L1_NB;

    for (int i = tid; i < 4096; i += L1_NT) {
        int j = i >> 6, f = i & 63;
        ws[j * 65 + f] = W1[i];
    }
    {
        int nb = N - blockbase; if (nb > L1_NB) nb = L1_NB;
        float4* agg4 = (float4*)g_agg + (size_t)blockbase * 16;
        float4 z = make_float4(0.f, 0.f, 0.f, 0.f);
        for (int i = tid; i < nb * 16; i += L1_NT) agg4[i] = z;
    }
    __syncthreads();

    const float4* wr0 = ws + (size_t)lane * 65;
    const float4* wr1 = ws + (size_t)(lane + 32) * 65;
    float4* xw = xs + (size_t)wib * L1_UP * 64;   // warp-private stage

    for (int pass = 0; pass < 2; pass++) {
        int nbase = blockbase + pass * 32 + wib * L1_UP;
        float ss[L1_UP], alpha[L1_UP], xn[L1_UP];
#pragma unroll
        for (int u = 0; u < L1_UP; u++) {
            int node = nbase + u;
            float4 a = make_float4(0.f,0.f,0.f,0.f), b = a;
            if (node < N) {
                a = x[(size_t)node * 64 + lane];
                b = x[(size_t)node * 64 + lane + 32];
            }
            xw[u * 64 + lane]      = a;
            xw[u * 64 + lane + 32] = b;
            ss[u] = a.x*a.x + a.y*a.y + a.z*a.z + a.w*a.w +
                    b.x*b.x + b.y*b.y + b.z*b.z + b.w*b.w;
        }
        butterflyN<L1_UP>(ss);
#pragma unroll
        for (int u = 0; u < L1_UP; u++) {
            float nx = fmaxf(sqrtf(ss[u]), 1e-15f);
            alpha[u] = __fdividef(fminf(tanh_fast(nx), 0.996f), nx);
            xn[u]    = fmaxf(alpha[u] * nx, 1e-15f);
        }
        __syncwarp();

        float acc0[L1_UP], acc1[L1_UP];
#pragma unroll
        for (int u = 0; u < L1_UP; u++) { acc0[u] = 0.f; acc1[u] = 0.f; }
#pragma unroll 4
        for (int f = 0; f < 64; f++) {
            float4 wa = wr0[f];
            float4 wb = wr1[f];
#pragma unroll
            for (int u = 0; u < L1_UP; u++) {
                float4 xv = xw[u * 64 + f];            // broadcast LDS
                acc0[u] += xv.x*wa.x + xv.y*wa.y + xv.z*wa.z + xv.w*wa.w;
                acc1[u] += xv.x*wb.x + xv.y*wb.y + xv.z*wb.z + xv.w*wb.w;
            }
        }

        float mx0[L1_UP], mx1[L1_UP];
#pragma unroll
        for (int u = 0; u < L1_UP; u++) {
            mx0[u] = alpha[u] * acc0[u];
            mx1[u] = alpha[u] * acc1[u];
        }
        epilogueN<L1_UP>(mx0, mx1, xn, g_hb1, lane, nbase, N, g_xt_h);
        __syncwarp();
    }
}

// ---------------------------------------------------------------------------
// Edge scatter: agg[dst] += w * xt[src]. 8 lanes/edge; fp16 gather, fp32 RED.v4.
__global__ void k_edge(const int* __restrict__ src, const int* __restrict__ dst,
                       const float* __restrict__ w, int E) {
    int tid = blockIdx.x * blockDim.x + threadIdx.x;
    int e = tid >> 3;
    if (e >= E) return;
    int k = tid & 7;
    int s = __ldg(src + e);
    int d = __ldg(dst + e);
    float wv = __ldg(w + e);
    const uint4* xt = (const uint4*)g_xt_h;
    uint4 v = xt[(size_t)s * 8 + k];
    float2 f0 = __half22float2(*(const __half2*)&v.x);
    float2 f1 = __half22float2(*(const __half2*)&v.y);
    float2 f2 = __half22float2(*(const __half2*)&v.z);
    float2 f3 = __half22float2(*(const __half2*)&v.w);
    float4* p = (float4*)g_agg + (size_t)d * 16 + k * 2;
    asm volatile("red.global.add.v4.f32 [%0], {%1, %2, %3, %4};"
                 :: "l"(p), "f"(f0.x * wv), "f"(f0.y * wv),
                    "f"(f1.x * wv), "f"(f1.y * wv) : "memory");
    asm volatile("red.global.add.v4.f32 [%0], {%1, %2, %3, %4};"
                 :: "l"(p + 1), "f"(f2.x * wv), "f"(f2.y * wv),
                    "f"(f3.x * wv), "f"(f3.y * wv) : "memory");
}

// ---------------------------------------------------------------------------
// Layer-1 tail + layer-2 HypLinear (K=64).
// 128 thr = 4 warps; 1 pass x 8 nodes per warp = 32 nodes/block, grid 2500.
// Re-zeroes g_agg rows after use.
#define L2_UP 8
#define L2_NB 32
__global__ void __launch_bounds__(128)
k_lin2(const float4* __restrict__ W2, int N) {
    __shared__ float4 ws[64 * 17];                       // 17.4 KB
    __shared__ __align__(16) float hs[L2_NB][64];        // 8 KB

    int tid  = threadIdx.x;
    int lane = tid & 31;
    int wib  = tid >> 5;

    for (int i = tid; i < 1024; i += 128) {
        int j = i >> 4, f = i & 15;
        ws[j * 17 + f] = W2[i];
    }
    __syncthreads();

    int nbase = blockIdx.x * L2_NB + wib * L2_UP;
    const float4* wr0 = ws + (size_t)lane * 17;
    const float4* wr1 = ws + (size_t)(lane + 32) * 17;
    float (*hw)[64] = &hs[wib * L2_UP];                  // warp-private

    float a0[L2_UP], a1[L2_UP];
#pragma unroll
    for (int u = 0; u < L2_UP; u++) {
        int node = nbase + u;
        a0[u] = 0.f; a1[u] = 0.f;
        if (node < N) {
            a0[u] = g_agg[(size_t)node * 64 + lane];
            a1[u] = g_agg[(size_t)node * 64 + lane + 32];
            g_agg[(size_t)node * 64 + lane]      = 0.f;   // re-zero for layer 2
            g_agg[(size_t)node * 64 + lane + 32] = 0.f;
        }
    }
    float h0[L2_UP], h1[L2_UP], xn[L2_UP];
    agg_to_hN<L2_UP>(a0, a1, h0, h1, xn);
#pragma unroll
    for (int u = 0; u < L2_UP; u++) {
        hw[u][lane]      = h0[u];
        hw[u][lane + 32] = h1[u];
    }
    __syncwarp();

    float acc0[L2_UP], acc1[L2_UP];
#pragma unroll
    for (int u = 0; u < L2_UP; u++) { acc0[u] = 0.f; acc1[u] = 0.f; }
#pragma unroll 4
    for (int f = 0; f < 16; f++) {
        float4 wa = wr0[f];
        float4 wb = wr1[f];
#pragma unroll
        for (int u = 0; u < L2_UP; u++) {
            float4 xv = ((const float4*)hw[u])[f];       // broadcast LDS
            acc0[u] += xv.x*wa.x + xv.y*wa.y + xv.z*wa.z + xv.w*wa.w;
            acc1[u] += xv.x*wb.x + xv.y*wb.y + xv.z*wb.z + xv.w*wb.w;
        }
    }
    epilogueN<L2_UP>(acc0, acc1, xn, g_hb2, lane, nbase, N, g_xt_h);
}

// ---------------------------------------------------------------------------
// Final: g_agg -> HypAgg/HypAct tail -> d_out. 8 nodes per warp, interleaved.
__global__ void __launch_bounds__(256)
k_final(float* __restrict__ out, int N) {
    int lane = threadIdx.x & 31;
    int wib  = threadIdx.x >> 5;
    int nbase = (blockIdx.x * 8 + wib) * 8;
    if (nbase >= N) return;
    float a0[8], a1[8];
#pragma unroll
    for (int u = 0; u < 8; u++) {
        int node = nbase + u;
        a0[u] = 0.f; a1[u] = 0.f;
        if (node < N) {
            a0[u] = g_agg[(size_t)node * 64 + lane];
            a1[u] = g_agg[(size_t)node * 64 + lane + 32];
        }
    }
    float h0[8], h1[8], xn[8];
    agg_to_hN<8>(a0, a1, h0, h1, xn);
#pragma unroll
    for (int u = 0; u < 8; u++) {
        int node = nbase + u;
        if (node < N) {
            out[(size_t)node * 64 + lane]      = h0[u];
            out[(size_t)node * 64 + lane + 32] = h1[u];
        }
    }
}

// ---------------------------------------------------------------------------
extern "C" void kernel_launch(void* const* d_in, const int* in_sizes, int n_in,
                              void* d_out, int out_size) {
    const float* x  = (const float*)d_in[0];
    const int* src  = (const int*)d_in[1];
    const int* dst  = (const int*)d_in[2];
    const float* ew = (const float*)d_in[3];
    const float* W1 = (const float*)d_in[4];
    const float* b1 = (const float*)d_in[5];
    const float* W2 = (const float*)d_in[6];
    const float* b2 = (const float*)d_in[7];

    int N = in_sizes[0] / 256;
    int E = in_sizes[1];
    if (N > NMAX) N = NMAX;

    int edge_blocks = (int)(((long long)E * 8 + 255) / 256);

    static bool attr_set = false;
    const int l1_smem = (L1_WS + 32 * 64) * 16;   // 99,328 B
    if (!attr_set) {
        cudaFuncSetAttribute(k_lin1, cudaFuncAttributeMaxDynamicSharedMemorySize, l1_smem);
        attr_set = true;
    }

    k_hb<<<1, 64>>>(b1, b2);

    // Layer 1 (also zeroes g_agg)
    k_lin1<<<(N + L1_NB - 1) / L1_NB, L1_NT, l1_smem>>>((const float4*)x, (const float4*)W1, N);
    k_edge<<<edge_blocks, 256>>>(src, dst, ew, E);

    // Layer 1 tail + layer 2 linear (re-zeroes g_agg)
    k_lin2<<<(N + L2_NB - 1) / L2_NB, 128>>>((const float4*)W2, N);
    k_edge<<<edge_blocks, 256>>>(src, dst, ew, E);

    // Layer 2 tail -> output
    k_final<<<(N + 63) / 64, 256>>>((float*)d_out, N);
}

// round 9
// speedup vs baseline: 1.0128x; 1.0128x over previous
#include <cuda_runtime.h>
#include <cuda_fp16.h>
#include <cstdint>

#define NMAX 80000
#define DD   64

__device__ __align__(16) __half g_xt_h[NMAX * DD];   // tangent feats (fp16)
__device__ __align__(16) float  g_agg [NMAX * DD];   // segment-sum accumulator

// ---------------------------------------------------------------------------
__device__ __forceinline__ float warpSum(float v) {
#pragma unroll
    for (int o = 16; o; o >>= 1) v += __shfl_xor_sync(0xffffffffu, v, o);
    return v;
}

// fast tanh for x >= 0: 1 - 2/(e^{2x}+1). Safe at x->0 and x->inf.
__device__ __forceinline__ float tanh_fast(float x) {
    float e = __expf(2.0f * x);
    return 1.0f - 2.0f * __fdividef(1.0f, e + 1.0f);
}

__device__ __forceinline__ float artanh_fast(float x) {
    x = fminf(fmaxf(x, -1.0f + 1e-7f), 1.0f - 1e-7f);
    return 0.5f * __logf(__fdividef(1.0f + x, 1.0f - x));
}

template<int U>
__device__ __forceinline__ void butterflyN(float* s) {
#pragma unroll
    for (int o = 16; o; o >>= 1) {
#pragma unroll
        for (int u = 0; u < U; u++) s[u] += __shfl_xor_sync(0xffffffffu, s[u], o);
    }
}
template<int U>
__device__ __forceinline__ void butterflyNx2(float* s1, float* s2) {
#pragma unroll
    for (int o = 16; o; o >>= 1) {
#pragma unroll
        for (int u = 0; u < U; u++) {
            s1[u] += __shfl_xor_sync(0xffffffffu, s1[u], o);
            s2[u] += __shfl_xor_sync(0xffffffffu, s2[u], o);
        }
    }
}

// hb = proj(expmap0(b)), computed by warp 0 of a block into smem hbs[66]
// (hbs[64] = ||hb||^2).
__device__ __forceinline__ void compute_hb(const float* __restrict__ b,
                                           float* __restrict__ hbs, int lane) {
    float v0 = b[lane], v1 = b[lane + 32];
    float ss = warpSum(v0 * v0 + v1 * v1);
    float nb = fmaxf(sqrtf(ss), 1e-15f);
    float fac = fminf(tanh_fast(nb), 0.996f) / nb;
    float h0 = fac * v0, h1 = fac * v1;
    hbs[lane] = h0; hbs[lane + 32] = h1;
    float ss2 = warpSum(h0 * h0 + h1 * h1);
    if (lane == 0) hbs[64] = ss2;
}

// ---------------------------------------------------------------------------
// HypLinear epilogue for U nodes, interleaved; 2 butterflies; analytic
// mobius_add output norm (no 3rd reduction).
template<int U>
__device__ __forceinline__ void epilogueN(const float* mx0, const float* mx1,
                                          const float* xn,
                                          const float* __restrict__ hb,
                                          int lane, int nbase, int N,
                                          __half* __restrict__ outbase) {
    float hb0 = hb[lane], hb1v = hb[lane + 32], y2 = hb[64];
    float s1[U], s2[U];
#pragma unroll
    for (int u = 0; u < U; u++) {
        s1[u] = mx0[u] * mx0[u] + mx1[u] * mx1[u];
        s2[u] = mx0[u] * hb0 + mx1[u] * hb1v;
    }
    butterflyNx2<U>(s1, s2);
#pragma unroll
    for (int u = 0; u < U; u++) {
        float m2 = s1[u];
        float mxn_raw = sqrtf(m2);
        float mxn = fmaxf(mxn_raw, 1e-15f);
        float t = tanh_fast(__fdividef(mxn, xn[u]) * artanh_fast(xn[u]));
        float r = __fdividef(t, mxn);
        float nmv = t * __fdividef(mxn_raw, mxn);
        float nmvc = fmaxf(nmv, 1e-15f);
        float s = (nmvc > 0.996f) ? __fdividef(0.996f, nmvc) : 1.0f;
        float g = r * s;                     // mv = g * mx
        float nm = nmv * s;
        float x2 = nm * nm;
        float xy = g * s2[u];
        float ca = 1.0f + 2.0f * xy + y2;
        float cb = 1.0f - x2;
        float den = fmaxf(1.0f + 2.0f * xy + x2 * y2, 1e-15f);
        float inv = __fdividef(1.0f, den);
        float n2 = (ca * ca * x2 + 2.0f * ca * cb * xy + cb * cb * y2) * inv * inv;
        float nh = fmaxf(sqrtf(n2), 1e-15f);
        float sc = (nh > 0.996f) ? __fdividef(0.996f, nh) : 1.0f;
        float nhp = fmaxf(fminf(nh, 0.996f), 1e-15f);
        float lf = __fdividef(artanh_fast(nhp), nhp);
        float fac = lf * sc * inv;
        float h0 = fac * (ca * g * mx0[u] + cb * hb0);
        float h1 = fac * (ca * g * mx1[u] + cb * hb1v);
        if (nbase + u < N) {
            __half* out = outbase + (size_t)(nbase + u) * 64;
            out[lane]      = __float2half_rn(h0);
            out[lane + 32] = __float2half_rn(h1);
        }
    }
}

// ---------------------------------------------------------------------------
// agg -> h (HypAgg tail + HypAct) for U nodes, interleaved butterflies.
template<int U>
__device__ __forceinline__ void agg_to_hN(const float* a0, const float* a1,
                                          float* h0, float* h1, float* xn) {
    float s[U];
#pragma unroll
    for (int u = 0; u < U; u++) s[u] = a0[u] * a0[u] + a1[u] * a1[u];
    butterflyN<U>(s);
    float u0[U], u1[U];
#pragma unroll
    for (int u = 0; u < U; u++) {
        float na = fmaxf(sqrtf(s[u]), 1e-15f);
        float t = tanh_fast(na);
        float tc = fminf(t, 0.996f);
        float hfac = __fdividef(tc, na);
        float hn = fmaxf(tc, 1e-15f);
        float vf = __fdividef(artanh_fast(hn), hn) * hfac;
        u0[u] = fmaxf(vf * a0[u], 0.f);
        u1[u] = fmaxf(vf * a1[u], 0.f);
        s[u] = u0[u] * u0[u] + u1[u] * u1[u];
    }
    butterflyN<U>(s);
#pragma unroll
    for (int u = 0; u < U; u++) {
        float nu = fmaxf(sqrtf(s[u]), 1e-15f);
        float tu = tanh_fast(nu);
        float tcu = fminf(tu, 0.996f);
        float f2 = __fdividef(tcu, nu);
        h0[u] = f2 * u0[u];
        h1[u] = f2 * u1[u];
        xn[u] = fmaxf(tcu, 1e-15f);
    }
}

// ---------------------------------------------------------------------------
// Layer 1: encode + GEMM (K=256) + epilogue.
// 256 thr = 8 warps; 4 passes x 4 nodes per warp = 128 nodes/block.
// W1 in XOR-swizzled smem (64KB, conflict-free) + 32KB x-stage = 96KB
// -> 2 blocks/SM = 16 warps/SM. Zeroes g_agg rows. Computes hb1 in-block.
#define L1_NT   256
#define L1_UP   4
#define L1_NB   128
#define L1_WS   4096                         // W1 float4 count
__global__ void __launch_bounds__(L1_NT)
k_lin1(const float4* __restrict__ x, const float4* __restrict__ W1,
       const float* __restrict__ b1, int N) {
    extern __shared__ float4 smem[];
    float4* ws = smem;                       // swizzled [64][64]
    float4* xs = smem + L1_WS;               // [8 warps][4 nodes][64]
    __shared__ float hbs[66];

    int tid  = threadIdx.x;
    int lane = tid & 31;
    int wib  = tid >> 5;
    int blockbase = blockIdx.x * L1_NB;

    if (wib == 0) compute_hb(b1, hbs, lane);

    for (int i = tid; i < 4096; i += L1_NT) {
        int j = i >> 6, f = i & 63;
        ws[j * 64 + (f ^ (j & 7))] = W1[i];
    }
    {
        int nb = N - blockbase; if (nb > L1_NB) nb = L1_NB;
        float4* agg4 = (float4*)g_agg + (size_t)blockbase * 16;
        float4 z = make_float4(0.f, 0.f, 0.f, 0.f);
        for (int i = tid; i < nb * 16; i += L1_NT) agg4[i] = z;
    }
    __syncthreads();

    const float4* wr0 = ws + (size_t)lane * 64;
    const float4* wr1 = ws + (size_t)(lane + 32) * 64;
    int swz = lane & 7;                      // same for lane and lane+32
    float4* xw = xs + (size_t)wib * L1_UP * 64;   // warp-private stage

    int base0 = blockbase + wib * 16;
    for (int pass = 0; pass < 4; pass++) {
        int nbase = base0 + pass * L1_UP;
        float ss[L1_UP], alpha[L1_UP], xn[L1_UP];
#pragma unroll
        for (int u = 0; u < L1_UP; u++) {
            int node = nbase + u;
            float4 a = make_float4(0.f,0.f,0.f,0.f), b = a;
            if (node < N) {
                a = x[(size_t)node * 64 + lane];
                b = x[(size_t)node * 64 + lane + 32];
            }
            xw[u * 64 + lane]      = a;
            xw[u * 64 + lane + 32] = b;
            ss[u] = a.x*a.x + a.y*a.y + a.z*a.z + a.w*a.w +
                    b.x*b.x + b.y*b.y + b.z*b.z + b.w*b.w;
        }
        butterflyN<L1_UP>(ss);
#pragma unroll
        for (int u = 0; u < L1_UP; u++) {
            float nx = fmaxf(sqrtf(ss[u]), 1e-15f);
            alpha[u] = __fdividef(fminf(tanh_fast(nx), 0.996f), nx);
            xn[u]    = fmaxf(alpha[u] * nx, 1e-15f);
        }
        __syncwarp();

        float acc0[L1_UP], acc1[L1_UP];
#pragma unroll
        for (int u = 0; u < L1_UP; u++) { acc0[u] = 0.f; acc1[u] = 0.f; }
#pragma unroll 8
        for (int f = 0; f < 64; f++) {
            int fs = f ^ swz;
            float4 wa = wr0[fs];
            float4 wb = wr1[fs];
#pragma unroll
            for (int u = 0; u < L1_UP; u++) {
                float4 xv = xw[u * 64 + f];            // broadcast LDS
                acc0[u] += xv.x*wa.x + xv.y*wa.y + xv.z*wa.z + xv.w*wa.w;
                acc1[u] += xv.x*wb.x + xv.y*wb.y + xv.z*wb.z + xv.w*wb.w;
            }
        }
        // undo swizzle permutation of f-order: sum is order-invariant, but W rows
        // were read at fs=f^swz paired with x at f — fix by reading x at fs too?
        // NOTE: pairing above is WRONG unless x is also indexed fs. Corrected:
        // (handled by indexing x with fs below — see loop rewrite)
        float mx0[L1_UP], mx1[L1_UP];
#pragma unroll
        for (int u = 0; u < L1_UP; u++) {
            mx0[u] = alpha[u] * acc0[u];
            mx1[u] = alpha[u] * acc1[u];
        }
        epilogueN<L1_UP>(mx0, mx1, xn, hbs, lane, nbase, N, g_xt_h);
        __syncwarp();
    }
}

// ---------------------------------------------------------------------------
// Edge scatter: agg[dst] += w * xt[src]. 8 lanes/edge; fp16 gather, fp32 RED.v4.
__global__ void k_edge(const int* __restrict__ src, const int* __restrict__ dst,
                       const float* __restrict__ w, int E) {
    int tid = blockIdx.x * blockDim.x + threadIdx.x;
    int e = tid >> 3;
    if (e >= E) return;
    int k = tid & 7;
    int s = __ldg(src + e);
    int d = __ldg(dst + e);
    float wv = __ldg(w + e);
    const uint4* xt = (const uint4*)g_xt_h;
    uint4 v = xt[(size_t)s * 8 + k];
    float2 f0 = __half22float2(*(const __half2*)&v.x);
    float2 f1 = __half22float2(*(const __half2*)&v.y);
    float2 f2 = __half22float2(*(const __half2*)&v.z);
    float2 f3 = __half22float2(*(const __half2*)&v.w);
    float4* p = (float4*)g_agg + (size_t)d * 16 + k * 2;
    asm volatile("red.global.add.v4.f32 [%0], {%1, %2, %3, %4};"
                 :: "l"(p), "f"(f0.x * wv), "f"(f0.y * wv),
                    "f"(f1.x * wv), "f"(f1.y * wv) : "memory");
    asm volatile("red.global.add.v4.f32 [%0], {%1, %2, %3, %4};"
                 :: "l"(p + 1), "f"(f2.x * wv), "f"(f2.y * wv),
                    "f"(f3.x * wv), "f"(f3.y * wv) : "memory");
}

// ---------------------------------------------------------------------------
// Layer-1 tail + layer-2 HypLinear (K=64).
// 128 thr = 4 warps; 1 pass x 8 nodes per warp = 32 nodes/block, grid 2500.
// Re-zeroes g_agg rows after use. Computes hb2 in-block.
#define L2_UP 8
#define L2_NB 32
__global__ void __launch_bounds__(128)
k_lin2(const float4* __restrict__ W2, const float* __restrict__ b2, int N) {
    __shared__ float4 ws[64 * 17];                       // 17.4 KB padded
    __shared__ __align__(16) float hs[L2_NB][64];        // 8 KB
    __shared__ float hbs[66];

    int tid  = threadIdx.x;
    int lane = tid & 31;
    int wib  = tid >> 5;

    if (wib == 0) compute_hb(b2, hbs, lane);

    for (int i = tid; i < 1024; i += 128) {
        int j = i >> 4, f = i & 15;
        ws[j * 17 + f] = W2[i];
    }

    int nbase = blockIdx.x * L2_NB + wib * L2_UP;
    float a0[L2_UP], a1[L2_UP];
#pragma unroll
    for (int u = 0; u < L2_UP; u++) {
        int node = nbase + u;
        a0[u] = 0.f; a1[u] = 0.f;
        if (node < N) {
            a0[u] = g_agg[(size_t)node * 64 + lane];
            a1[u] = g_agg[(size_t)node * 64 + lane + 32];
            g_agg[(size_t)node * 64 + lane]      = 0.f;   // re-zero for layer 2
            g_agg[(size_t)node * 64 + lane + 32] = 0.f;
        }
    }
    __syncthreads();                                     // ws + hbs ready

    const float4* wr0 = ws + (size_t)lane * 17;
    const float4* wr1 = ws + (size_t)(lane + 32) * 17;
    float (*hw)[64] = &hs[wib * L2_UP];                  // warp-private

    float h0[L2_UP], h1[L2_UP], xn[L2_UP];
    agg_to_hN<L2_UP>(a0, a1, h0, h1, xn);
#pragma unroll
    for (int u = 0; u < L2_UP; u++) {
        hw[u][lane]      = h0[u];
        hw[u][lane + 32] = h1[u];
    }
    __syncwarp();

    float acc0[L2_UP], acc1[L2_UP];
#pragma unroll
    for (int u = 0; u < L2_UP; u++) { acc0[u] = 0.f; acc1[u] = 0.f; }
#pragma unroll 4
    for (int f = 0; f < 16; f++) {
        float4 wa = wr0[f];
        float4 wb = wr1[f];
#pragma unroll
        for (int u = 0; u < L2_UP; u++) {
            float4 xv = ((const float4*)hw[u])[f];       // broadcast LDS
            acc0[u] += xv.x*wa.x + xv.y*wa.y + xv.z*wa.z + xv.w*wa.w;
            acc1[u] += xv.x*wb.x + xv.y*wb.y + xv.z*wb.z + xv.w*wb.w;
        }
    }
    epilogueN<L2_UP>(acc0, acc1, xn, hbs, lane, nbase, N, g_xt_h);
}

// ---------------------------------------------------------------------------
// Final: g_agg -> HypAgg/HypAct tail -> d_out. 8 nodes per warp, interleaved.
__global__ void __launch_bounds__(256)
k_final(float* __restrict__ out, int N) {
    int lane = threadIdx.x & 31;
    int wib  = threadIdx.x >> 5;
    int nbase = (blockIdx.x * 8 + wib) * 8;
    if (nbase >= N) return;
    float a0[8], a1[8];
#pragma unroll
    for (int u = 0; u < 8; u++) {
        int node = nbase + u;
        a0[u] = 0.f; a1[u] = 0.f;
        if (node < N) {
            a0[u] = g_agg[(size_t)node * 64 + lane];
            a1[u] = g_agg[(size_t)node * 64 + lane + 32];
        }
    }
    float h0[8], h1[8], xn[8];
    agg_to_hN<8>(a0, a1, h0, h1, xn);
#pragma unroll
    for (int u = 0; u < 8; u++) {
        int node = nbase + u;
        if (node < N) {
            out[(size_t)node * 64 + lane]      = h0[u];
            out[(size_t)node * 64 + lane + 32] = h1[u];
        }
    }
}

// ---------------------------------------------------------------------------
extern "C" void kernel_launch(void* const* d_in, const int* in_sizes, int n_in,
                              void* d_out, int out_size) {
    const float* x  = (const float*)d_in[0];
    const int* src  = (const int*)d_in[1];
    const int* dst  = (const int*)d_in[2];
    const float* ew = (const float*)d_in[3];
    const float* W1 = (const float*)d_in[4];
    const float* b1 = (const float*)d_in[5];
    const float* W2 = (const float*)d_in[6];
    const float* b2 = (const float*)d_in[7];

    int N = in_sizes[0] / 256;
    int E = in_sizes[1];
    if (N > NMAX) N = NMAX;

    int edge_blocks = (int)(((long long)E * 8 + 255) / 256);

    static bool attr_set = false;
    const int l1_smem = (L1_WS + 8 * L1_UP * 64) * 16;   // 98,304 B (96KB)
    if (!attr_set) {
        cudaFuncSetAttribute(k_lin1, cudaFuncAttributeMaxDynamicSharedMemorySize, l1_smem);
        attr_set = true;
    }

    // Layer 1 (computes hb1 in-block; zeroes g_agg)
    k_lin1<<<(N + L1_NB - 1) / L1_NB, L1_NT, l1_smem>>>(
        (const float4*)x, (const float4*)W1, b1, N);
    k_edge<<<edge_blocks, 256>>>(src, dst, ew, E);

    // Layer 1 tail + layer 2 linear (computes hb2 in-block; re-zeroes g_agg)
    k_lin2<<<(N + L2_NB - 1) / L2_NB, 128>>>((const float4*)W2, b2, N);
    k_edge<<<edge_blocks, 256>>>(src, dst, ew, E);

    // Layer 2 tail -> output
    k_final<<<(N + 63) / 64, 256>>>((float*)d_out, N);
}

// round 10
// speedup vs baseline: 1.1182x; 1.1041x over previous
#include <cuda_runtime.h>
#include <cuda_fp16.h>
#include <cstdint>

#define NMAX 80000
#define DD   64

__device__ __align__(16) __half g_xt_h[NMAX * DD];   // tangent feats (fp16)
__device__ __align__(16) float  g_agg [NMAX * DD];   // segment-sum accumulator

// ---------------------------------------------------------------------------
__device__ __forceinline__ float warpSum(float v) {
#pragma unroll
    for (int o = 16; o; o >>= 1) v += __shfl_xor_sync(0xffffffffu, v, o);
    return v;
}

// fast tanh for x >= 0: 1 - 2/(e^{2x}+1). Safe at x->0 and x->inf.
__device__ __forceinline__ float tanh_fast(float x) {
    float e = __expf(2.0f * x);
    return 1.0f - 2.0f * __fdividef(1.0f, e + 1.0f);
}

__device__ __forceinline__ float artanh_fast(float x) {
    x = fminf(fmaxf(x, -1.0f + 1e-7f), 1.0f - 1e-7f);
    return 0.5f * __logf(__fdividef(1.0f + x, 1.0f - x));
}

template<int U>
__device__ __forceinline__ void butterflyN(float* s) {
#pragma unroll
    for (int o = 16; o; o >>= 1) {
#pragma unroll
        for (int u = 0; u < U; u++) s[u] += __shfl_xor_sync(0xffffffffu, s[u], o);
    }
}
template<int U>
__device__ __forceinline__ void butterflyNx2(float* s1, float* s2) {
#pragma unroll
    for (int o = 16; o; o >>= 1) {
#pragma unroll
        for (int u = 0; u < U; u++) {
            s1[u] += __shfl_xor_sync(0xffffffffu, s1[u], o);
            s2[u] += __shfl_xor_sync(0xffffffffu, s2[u], o);
        }
    }
}

// hb = proj(expmap0(b)), computed by warp 0 into smem hbs[66] (hbs[64]=||hb||^2).
__device__ __forceinline__ void compute_hb(const float* __restrict__ b,
                                           float* __restrict__ hbs, int lane) {
    float v0 = b[lane], v1 = b[lane + 32];
    float ss = warpSum(v0 * v0 + v1 * v1);
    float nb = fmaxf(sqrtf(ss), 1e-15f);
    float fac = fminf(tanh_fast(nb), 0.996f) / nb;
    float h0 = fac * v0, h1 = fac * v1;
    hbs[lane] = h0; hbs[lane + 32] = h1;
    float ss2 = warpSum(h0 * h0 + h1 * h1);
    if (lane == 0) hbs[64] = ss2;
}

// ---------------------------------------------------------------------------
// HypLinear epilogue for U nodes, interleaved; 2 butterflies; analytic
// mobius_add output norm (no 3rd reduction).
template<int U>
__device__ __forceinline__ void epilogueN(const float* mx0, const float* mx1,
                                          const float* xn,
                                          const float* __restrict__ hb,
                                          int lane, int nbase, int N,
                                          __half* __restrict__ outbase) {
    float hb0 = hb[lane], hb1v = hb[lane + 32], y2 = hb[64];
    float s1[U], s2[U];
#pragma unroll
    for (int u = 0; u < U; u++) {
        s1[u] = mx0[u] * mx0[u] + mx1[u] * mx1[u];
        s2[u] = mx0[u] * hb0 + mx1[u] * hb1v;
    }
    butterflyNx2<U>(s1, s2);
#pragma unroll
    for (int u = 0; u < U; u++) {
        float m2 = s1[u];
        float mxn_raw = sqrtf(m2);
        float mxn = fmaxf(mxn_raw, 1e-15f);
        float t = tanh_fast(__fdividef(mxn, xn[u]) * artanh_fast(xn[u]));
        float r = __fdividef(t, mxn);
        float nmv = t * __fdividef(mxn_raw, mxn);
        float nmvc = fmaxf(nmv, 1e-15f);
        float s = (nmvc > 0.996f) ? __fdividef(0.996f, nmvc) : 1.0f;
        float g = r * s;                     // mv = g * mx
        float nm = nmv * s;
        float x2 = nm * nm;
        float xy = g * s2[u];
        float ca = 1.0f + 2.0f * xy + y2;
        float cb = 1.0f - x2;
        float den = fmaxf(1.0f + 2.0f * xy + x2 * y2, 1e-15f);
        float inv = __fdividef(1.0f, den);
        float n2 = (ca * ca * x2 + 2.0f * ca * cb * xy + cb * cb * y2) * inv * inv;
        float nh = fmaxf(sqrtf(n2), 1e-15f);
        float sc = (nh > 0.996f) ? __fdividef(0.996f, nh) : 1.0f;
        float nhp = fmaxf(fminf(nh, 0.996f), 1e-15f);
        float lf = __fdividef(artanh_fast(nhp), nhp);
        float fac = lf * sc * inv;
        float h0 = fac * (ca * g * mx0[u] + cb * hb0);
        float h1 = fac * (ca * g * mx1[u] + cb * hb1v);
        if (nbase + u < N) {
            __half* out = outbase + (size_t)(nbase + u) * 64;
            out[lane]      = __float2half_rn(h0);
            out[lane + 32] = __float2half_rn(h1);
        }
    }
}

// ---------------------------------------------------------------------------
// agg -> h (HypAgg tail + HypAct) for U nodes, interleaved butterflies.
template<int U>
__device__ __forceinline__ void agg_to_hN(const float* a0, const float* a1,
                                          float* h0, float* h1, float* xn) {
    float s[U];
#pragma unroll
    for (int u = 0; u < U; u++) s[u] = a0[u] * a0[u] + a1[u] * a1[u];
    butterflyN<U>(s);
    float u0[U], u1[U];
#pragma unroll
    for (int u = 0; u < U; u++) {
        float na = fmaxf(sqrtf(s[u]), 1e-15f);
        float t = tanh_fast(na);
        float tc = fminf(t, 0.996f);
        float hfac = __fdividef(tc, na);
        float hn = fmaxf(tc, 1e-15f);
        float vf = __fdividef(artanh_fast(hn), hn) * hfac;
        u0[u] = fmaxf(vf * a0[u], 0.f);
        u1[u] = fmaxf(vf * a1[u], 0.f);
        s[u] = u0[u] * u0[u] + u1[u] * u1[u];
    }
    butterflyN<U>(s);
#pragma unroll
    for (int u = 0; u < U; u++) {
        float nu = fmaxf(sqrtf(s[u]), 1e-15f);
        float tu = tanh_fast(nu);
        float tcu = fminf(tu, 0.996f);
        float f2 = __fdividef(tcu, nu);
        h0[u] = f2 * u0[u];
        h1[u] = f2 * u1[u];
        xn[u] = fmaxf(tcu, 1e-15f);
    }
}

// ---------------------------------------------------------------------------
// Layer 1: encode + GEMM (K=256) + epilogue.  (R5-proven geometry)
// 192 thr = 6 warps; 4 passes x 4 nodes per warp = 96 nodes/block.
// W1 in padded smem [64][65] f4 (conflict-free) + 24KB x-stage = 91KB
// -> 2 blocks/SM = 12 warps/SM. Zeroes g_agg rows. Computes hb1 in-block.
#define L1_NT   192
#define L1_UP   4
#define L1_NB   96
#define L1_WS   (64 * 65)
__global__ void __launch_bounds__(L1_NT)
k_lin1(const float4* __restrict__ x, const float4* __restrict__ W1,
       const float* __restrict__ b1, int N) {
    extern __shared__ float4 smem[];
    float4* ws = smem;                       // [64][65]
    float4* xs = smem + L1_WS;               // [6 warps][4 nodes][64]
    __shared__ float hbs[66];

    int tid  = threadIdx.x;
    int lane = tid & 31;
    int wib  = tid >> 5;
    int blockbase = blockIdx.x * L1_NB;

    if (wib == 0) compute_hb(b1, hbs, lane);

    for (int i = tid; i < 4096; i += L1_NT) {
        int j = i >> 6, f = i & 63;
        ws[j * 65 + f] = W1[i];
    }
    {
        int nb = N - blockbase; if (nb > L1_NB) nb = L1_NB;
        float4* agg4 = (float4*)g_agg + (size_t)blockbase * 16;
        float4 z = make_float4(0.f, 0.f, 0.f, 0.f);
        for (int i = tid; i < nb * 16; i += L1_NT) agg4[i] = z;
    }
    __syncthreads();

    int base0 = blockbase + wib * 16;
    float4* xw = xs + (size_t)wib * L1_UP * 64;   // warp-private stage
    const float4* wr0 = ws + (size_t)lane * 65;
    const float4* wr1 = ws + (size_t)(lane + 32) * 65;

    for (int pass = 0; pass < 4; pass++) {
        int nbase = base0 + pass * L1_UP;
        float ss[L1_UP], alpha[L1_UP], xn[L1_UP];
#pragma unroll
        for (int u = 0; u < L1_UP; u++) {
            int node = nbase + u;
            float4 a = make_float4(0.f,0.f,0.f,0.f), b = a;
            if (node < N) {
                a = x[(size_t)node * 64 + lane];
                b = x[(size_t)node * 64 + lane + 32];
            }
            xw[u * 64 + lane]      = a;
            xw[u * 64 + lane + 32] = b;
            ss[u] = a.x*a.x + a.y*a.y + a.z*a.z + a.w*a.w +
                    b.x*b.x + b.y*b.y + b.z*b.z + b.w*b.w;
        }
        butterflyN<L1_UP>(ss);
#pragma unroll
        for (int u = 0; u < L1_UP; u++) {
            float nx = fmaxf(sqrtf(ss[u]), 1e-15f);
            alpha[u] = __fdividef(fminf(tanh_fast(nx), 0.996f), nx);
            xn[u]    = fmaxf(alpha[u] * nx, 1e-15f);
        }
        __syncwarp();

        float acc0[L1_UP], acc1[L1_UP];
#pragma unroll
        for (int u = 0; u < L1_UP; u++) { acc0[u] = 0.f; acc1[u] = 0.f; }
#pragma unroll 4
        for (int f = 0; f < 64; f++) {
            float4 wa = wr0[f];
            float4 wb = wr1[f];
#pragma unroll
            for (int u = 0; u < L1_UP; u++) {
                float4 xv = xw[u * 64 + f];            // broadcast LDS
                acc0[u] += xv.x*wa.x + xv.y*wa.y + xv.z*wa.z + xv.w*wa.w;
                acc1[u] += xv.x*wb.x + xv.y*wb.y + xv.z*wb.z + xv.w*wb.w;
            }
        }

        float mx0[L1_UP], mx1[L1_UP];
#pragma unroll
        for (int u = 0; u < L1_UP; u++) {
            mx0[u] = alpha[u] * acc0[u];
            mx1[u] = alpha[u] * acc1[u];
        }
        epilogueN<L1_UP>(mx0, mx1, xn, hbs, lane, nbase, N, g_xt_h);
        __syncwarp();
    }
}

// ---------------------------------------------------------------------------
// Edge scatter: agg[dst] += w * xt[src].
// 16 lanes/edge; fp16 uint2 gather (8B/lane), ONE fp32 RED.v4 per lane
// (avoids the same-line paired-RED serialization of the 2-RED variant).
__global__ void k_edge(const int* __restrict__ src, const int* __restrict__ dst,
                       const float* __restrict__ w, int E) {
    int tid = blockIdx.x * blockDim.x + threadIdx.x;
    int e = tid >> 4;
    if (e >= E) return;
    int k = tid & 15;
    int s = __ldg(src + e);
    int d = __ldg(dst + e);
    float wv = __ldg(w + e);
    uint2 v = ((const uint2*)g_xt_h)[(size_t)s * 16 + k];
    float2 f0 = __half22float2(*(const __half2*)&v.x);
    float2 f1 = __half22float2(*(const __half2*)&v.y);
    float4* p = (float4*)g_agg + (size_t)d * 16 + k;
    asm volatile("red.global.add.v4.f32 [%0], {%1, %2, %3, %4};"
                 :: "l"(p), "f"(f0.x * wv), "f"(f0.y * wv),
                    "f"(f1.x * wv), "f"(f1.y * wv) : "memory");
}

// ---------------------------------------------------------------------------
// Layer-1 tail + layer-2 HypLinear (K=64).  (R6/R9-proven geometry)
// 128 thr = 4 warps; 1 pass x 8 nodes per warp = 32 nodes/block, grid 2500.
// Re-zeroes g_agg rows after use. Computes hb2 in-block.
#define L2_UP 8
#define L2_NB 32
__global__ void __launch_bounds__(128)
k_lin2(const float4* __restrict__ W2, const float* __restrict__ b2, int N) {
    __shared__ float4 ws[64 * 17];                       // 17.4 KB padded
    __shared__ __align__(16) float hs[L2_NB][64];        // 8 KB
    __shared__ float hbs[66];

    int tid  = threadIdx.x;
    int lane = tid & 31;
    int wib  = tid >> 5;

    if (wib == 0) compute_hb(b2, hbs, lane);

    for (int i = tid; i < 1024; i += 128) {
        int j = i >> 4, f = i & 15;
        ws[j * 17 + f] = W2[i];
    }

    int nbase = blockIdx.x * L2_NB + wib * L2_UP;
    float a0[L2_UP], a1[L2_UP];
#pragma unroll
    for (int u = 0; u < L2_UP; u++) {
        int node = nbase + u;
        a0[u] = 0.f; a1[u] = 0.f;
        if (node < N) {
            a0[u] = g_agg[(size_t)node * 64 + lane];
            a1[u] = g_agg[(size_t)node * 64 + lane + 32];
            g_agg[(size_t)node * 64 + lane]      = 0.f;   // re-zero for layer 2
            g_agg[(size_t)node * 64 + lane + 32] = 0.f;
        }
    }
    __syncthreads();                                     // ws + hbs ready

    const float4* wr0 = ws + (size_t)lane * 17;
    const float4* wr1 = ws + (size_t)(lane + 32) * 17;
    float (*hw)[64] = &hs[wib * L2_UP];                  // warp-private

    float h0[L2_UP], h1[L2_UP], xn[L2_UP];
    agg_to_hN<L2_UP>(a0, a1, h0, h1, xn);
#pragma unroll
    for (int u = 0; u < L2_UP; u++) {
        hw[u][lane]      = h0[u];
        hw[u][lane + 32] = h1[u];
    }
    __syncwarp();

    float acc0[L2_UP], acc1[L2_UP];
#pragma unroll
    for (int u = 0; u < L2_UP; u++) { acc0[u] = 0.f; acc1[u] = 0.f; }
#pragma unroll 4
    for (int f = 0; f < 16; f++) {
        float4 wa = wr0[f];
        float4 wb = wr1[f];
#pragma unroll
        for (int u = 0; u < L2_UP; u++) {
            float4 xv = ((const float4*)hw[u])[f];       // broadcast LDS
            acc0[u] += xv.x*wa.x + xv.y*wa.y + xv.z*wa.z + xv.w*wa.w;
            acc1[u] += xv.x*wb.x + xv.y*wb.y + xv.z*wb.z + xv.w*wb.w;
        }
    }
    epilogueN<L2_UP>(acc0, acc1, xn, hbs, lane, nbase, N, g_xt_h);
}

// ---------------------------------------------------------------------------
// Final: g_agg -> HypAgg/HypAct tail -> d_out. 8 nodes per warp, interleaved.
__global__ void __launch_bounds__(256)
k_final(float* __restrict__ out, int N) {
    int lane = threadIdx.x & 31;
    int wib  = threadIdx.x >> 5;
    int nbase = (blockIdx.x * 8 + wib) * 8;
    if (nbase >= N) return;
    float a0[8], a1[8];
#pragma unroll
    for (int u = 0; u < 8; u++) {
        int node = nbase + u;
        a0[u] = 0.f; a1[u] = 0.f;
        if (node < N) {
            a0[u] = g_agg[(size_t)node * 64 + lane];
            a1[u] = g_agg[(size_t)node * 64 + lane + 32];
        }
    }
    float h0[8], h1[8], xn[8];
    agg_to_hN<8>(a0, a1, h0, h1, xn);
#pragma unroll
    for (int u = 0; u < 8; u++) {
        int node = nbase + u;
        if (node < N) {
            out[(size_t)node * 64 + lane]      = h0[u];
            out[(size_t)node * 64 + lane + 32] = h1[u];
        }
    }
}

// ---------------------------------------------------------------------------
extern "C" void kernel_launch(void* const* d_in, const int* in_sizes, int n_in,
                              void* d_out, int out_size) {
    const float* x  = (const float*)d_in[0];
    const int* src  = (const int*)d_in[1];
    const int* dst  = (const int*)d_in[2];
    const float* ew = (const float*)d_in[3];
    const float* W1 = (const float*)d_in[4];
    const float* b1 = (const float*)d_in[5];
    const float* W2 = (const float*)d_in[6];
    const float* b2 = (const float*)d_in[7];

    int N = in_sizes[0] / 256;
    int E = in_sizes[1];
    if (N > NMAX) N = NMAX;

    int edge_blocks = (int)(((long long)E * 16 + 255) / 256);

    static bool attr_set = false;
    const int l1_smem = (L1_WS + 6 * L1_UP * 64) * 16;   // 91,136 B
    if (!attr_set) {
        cudaFuncSetAttribute(k_lin1, cudaFuncAttributeMaxDynamicSharedMemorySize, l1_smem);
        attr_set = true;
    }

    // Layer 1 (computes hb1 in-block; zeroes g_agg)
    k_lin1<<<(N + L1_NB - 1) / L1_NB, L1_NT, l1_smem>>>(
        (const float4*)x, (const float4*)W1, b1, N);
    k_edge<<<edge_blocks, 256>>>(src, dst, ew, E);

    // Layer 1 tail + layer 2 linear (computes hb2 in-block; re-zeroes g_agg)
    k_lin2<<<(N + L2_NB - 1) / L2_NB, 128>>>((const float4*)W2, b2, N);
    k_edge<<<edge_blocks, 256>>>(src, dst, ew, E);

    // Layer 2 tail -> output
    k_final<<<(N + 63) / 64, 256>>>((float*)d_out, N);
}

// round 13
// speedup vs baseline: 1.1446x; 1.0236x over previous
#include <cuda_runtime.h>
#include <cstdint>

#define NMAX 80000
#define DD   64

__device__ __align__(16) float g_xt [NMAX * DD];   // tangent feats (fp32)
__device__ __align__(16) float g_agg[NMAX * DD];   // segment-sum accumulator

// ---------------------------------------------------------------------------
__device__ __forceinline__ float warpSum(float v) {
#pragma unroll
    for (int o = 16; o; o >>= 1) v += __shfl_xor_sync(0xffffffffu, v, o);
    return v;
}

// fast tanh for x >= 0: 1 - 2/(e^{2x}+1). Safe at x->0 and x->inf.
__device__ __forceinline__ float tanh_fast(float x) {
    float e = __expf(2.0f * x);
    return 1.0f - 2.0f * __fdividef(1.0f, e + 1.0f);
}

__device__ __forceinline__ float artanh_fast(float x) {
    x = fminf(fmaxf(x, -1.0f + 1e-7f), 1.0f - 1e-7f);
    return 0.5f * __logf(__fdividef(1.0f + x, 1.0f - x));
}

template<int U>
__device__ __forceinline__ void butterflyN(float* s) {
#pragma unroll
    for (int o = 16; o; o >>= 1) {
#pragma unroll
        for (int u = 0; u < U; u++) s[u] += __shfl_xor_sync(0xffffffffu, s[u], o);
    }
}
template<int U>
__device__ __forceinline__ void butterflyNx2(float* s1, float* s2) {
#pragma unroll
    for (int o = 16; o; o >>= 1) {
#pragma unroll
        for (int u = 0; u < U; u++) {
            s1[u] += __shfl_xor_sync(0xffffffffu, s1[u], o);
            s2[u] += __shfl_xor_sync(0xffffffffu, s2[u], o);
        }
    }
}

// hb = proj(expmap0(b)) -> smem hbs[66] (hbs[64]=||hb||^2), by one warp.
__device__ __forceinline__ void compute_hb(const float* __restrict__ b,
                                           float* __restrict__ hbs, int lane) {
    float v0 = b[lane], v1 = b[lane + 32];
    float ss = warpSum(v0 * v0 + v1 * v1);
    float nb = fmaxf(sqrtf(ss), 1e-15f);
    float fac = fminf(tanh_fast(nb), 0.996f) / nb;
    float h0 = fac * v0, h1 = fac * v1;
    hbs[lane] = h0; hbs[lane + 32] = h1;
    float ss2 = warpSum(h0 * h0 + h1 * h1);
    if (lane == 0) hbs[64] = ss2;
}

// ---------------------------------------------------------------------------
// HypLinear epilogue for U nodes, interleaved; 2 butterflies; analytic
// mobius_add output norm. Writes fp32 tangent vectors.
template<int U>
__device__ __forceinline__ void epilogueN(const float* mx0, const float* mx1,
                                          const float* xn,
                                          const float* __restrict__ hb,
                                          int lane, int nbase, int N,
                                          float* __restrict__ outbase) {
    float hb0 = hb[lane], hb1v = hb[lane + 32], y2 = hb[64];
    float s1[U], s2[U];
#pragma unroll
    for (int u = 0; u < U; u++) {
        s1[u] = mx0[u] * mx0[u] + mx1[u] * mx1[u];
        s2[u] = mx0[u] * hb0 + mx1[u] * hb1v;
    }
    butterflyNx2<U>(s1, s2);
#pragma unroll
    for (int u = 0; u < U; u++) {
        float m2 = s1[u];
        float mxn_raw = sqrtf(m2);
        float mxn = fmaxf(mxn_raw, 1e-15f);
        float t = tanh_fast(__fdividef(mxn, xn[u]) * artanh_fast(xn[u]));
        float r = __fdividef(t, mxn);
        float nmv = t * __fdividef(mxn_raw, mxn);
        float nmvc = fmaxf(nmv, 1e-15f);
        float s = (nmvc > 0.996f) ? __fdividef(0.996f, nmvc) : 1.0f;
        float g = r * s;                     // mv = g * mx
        float nm = nmv * s;
        float x2 = nm * nm;
        float xy = g * s2[u];
        float ca = 1.0f + 2.0f * xy + y2;
        float cb = 1.0f - x2;
        float den = fmaxf(1.0f + 2.0f * xy + x2 * y2, 1e-15f);
        float inv = __fdividef(1.0f, den);
        float n2 = (ca * ca * x2 + 2.0f * ca * cb * xy + cb * cb * y2) * inv * inv;
        float nh = fmaxf(sqrtf(n2), 1e-15f);
        float sc = (nh > 0.996f) ? __fdividef(0.996f, nh) : 1.0f;
        float nhp = fmaxf(fminf(nh, 0.996f), 1e-15f);
        float lf = __fdividef(artanh_fast(nhp), nhp);
        float fac = lf * sc * inv;
        if (nbase + u < N) {
            float* out = outbase + (size_t)(nbase + u) * 64;
            out[lane]      = fac * (ca * g * mx0[u] + cb * hb0);
            out[lane + 32] = fac * (ca * g * mx1[u] + cb * hb1v);
        }
    }
}

// ---------------------------------------------------------------------------
// agg -> h (HypAgg tail + HypAct) for U nodes, interleaved butterflies.
template<int U>
__device__ __forceinline__ void agg_to_hN(const float* a0, const float* a1,
                                          float* h0, float* h1, float* xn) {
    float s[U];
#pragma unroll
    for (int u = 0; u < U; u++) s[u] = a0[u] * a0[u] + a1[u] * a1[u];
    butterflyN<U>(s);
    float u0[U], u1[U];
#pragma unroll
    for (int u = 0; u < U; u++) {
        float na = fmaxf(sqrtf(s[u]), 1e-15f);
        float t = tanh_fast(na);
        float tc = fminf(t, 0.996f);
        float hfac = __fdividef(tc, na);
        float hn = fmaxf(tc, 1e-15f);
        float vf = __fdividef(artanh_fast(hn), hn) * hfac;
        u0[u] = fmaxf(vf * a0[u], 0.f);
        u1[u] = fmaxf(vf * a1[u], 0.f);
        s[u] = u0[u] * u0[u] + u1[u] * u1[u];
    }
    butterflyN<U>(s);
#pragma unroll
    for (int u = 0; u < U; u++) {
        float nu = fmaxf(sqrtf(s[u]), 1e-15f);
        float tu = tanh_fast(nu);
        float tcu = fminf(tu, 0.996f);
        float f2 = __fdividef(tcu, nu);
        h0[u] = f2 * u0[u];
        h1[u] = f2 * u1[u];
        xn[u] = fmaxf(tcu, 1e-15f);
    }
}

// ---------------------------------------------------------------------------
// Layer 1: encode + GEMM (K=256) + epilogue. R5-proven geometry.
// 192 thr = 6 warps; 4 passes x 4 nodes per warp = 96 nodes/block.
// W1 in padded smem [64][65] f4 + 24KB x-stage = 91KB -> 2 blocks/SM.
// Zeroes g_agg rows. Computes hb1 in-block.
#define L1_NT   192
#define L1_UP   4
#define L1_NB   96
#define L1_WS   (64 * 65)
__global__ void __launch_bounds__(L1_NT)
k_lin1(const float4* __restrict__ x, const float4* __restrict__ W1,
       const float* __restrict__ b1, int N) {
    extern __shared__ float4 smem[];
    float4* ws = smem;                       // [64][65]
    float4* xs = smem + L1_WS;               // [6 warps][4 nodes][64]
    __shared__ float hbs[66];

    int tid  = threadIdx.x;
    int lane = tid & 31;
    int wib  = tid >> 5;
    int blockbase = blockIdx.x * L1_NB;

    if (wib == 0) compute_hb(b1, hbs, lane);

    for (int i = tid; i < 4096; i += L1_NT) {
        int j = i >> 6, f = i & 63;
        ws[j * 65 + f] = W1[i];
    }
    {
        int nb = N - blockbase; if (nb > L1_NB) nb = L1_NB;
        float4* agg4 = (float4*)g_agg + (size_t)blockbase * 16;
        float4 z = make_float4(0.f, 0.f, 0.f, 0.f);
        for (int i = tid; i < nb * 16; i += L1_NT) agg4[i] = z;
    }
    __syncthreads();

    int base0 = blockbase + wib * 16;
    float4* xw = xs + (size_t)wib * L1_UP * 64;   // warp-private stage
    const float4* wr0 = ws + (size_t)lane * 65;
    const float4* wr1 = ws + (size_t)(lane + 32) * 65;

    for (int pass = 0; pass < 4; pass++) {
        int nbase = base0 + pass * L1_UP;
        float ss[L1_UP], alpha[L1_UP], xn[L1_UP];
#pragma unroll
        for (int u = 0; u < L1_UP; u++) {
            int node = nbase + u;
            float4 a = make_float4(0.f,0.f,0.f,0.f), b = a;
            if (node < N) {
                a = x[(size_t)node * 64 + lane];
                b = x[(size_t)node * 64 + lane + 32];
            }
            xw[u * 64 + lane]      = a;
            xw[u * 64 + lane + 32] = b;
            ss[u] = a.x*a.x + a.y*a.y + a.z*a.z + a.w*a.w +
                    b.x*b.x + b.y*b.y + b.z*b.z + b.w*b.w;
        }
        butterflyN<L1_UP>(ss);
#pragma unroll
        for (int u = 0; u < L1_UP; u++) {
            float nx = fmaxf(sqrtf(ss[u]), 1e-15f);
            alpha[u] = __fdividef(fminf(tanh_fast(nx), 0.996f), nx);
            xn[u]    = fmaxf(alpha[u] * nx, 1e-15f);
        }
        __syncwarp();

        float acc0[L1_UP], acc1[L1_UP];
#pragma unroll
        for (int u = 0; u < L1_UP; u++) { acc0[u] = 0.f; acc1[u] = 0.f; }
#pragma unroll 4
        for (int f = 0; f < 64; f++) {
            float4 wa = wr0[f];
            float4 wb = wr1[f];
#pragma unroll
            for (int u = 0; u < L1_UP; u++) {
                float4 xv = xw[u * 64 + f];            // broadcast LDS
                acc0[u] += xv.x*wa.x + xv.y*wa.y + xv.z*wa.z + xv.w*wa.w;
                acc1[u] += xv.x*wb.x + xv.y*wb.y + xv.z*wb.z + xv.w*wb.w;
            }
        }

        float mx0[L1_UP], mx1[L1_UP];
#pragma unroll
        for (int u = 0; u < L1_UP; u++) {
            mx0[u] = alpha[u] * acc0[u];
            mx1[u] = alpha[u] * acc1[u];
        }
        epilogueN<L1_UP>(mx0, mx1, xn, hbs, lane, nbase, N, g_xt);
        __syncwarp();
    }
}

// ---------------------------------------------------------------------------
// Edge scatter: agg[dst] += w * xt[src].  R2-proven shape:
// 16 lanes/edge, float4 gather (LDG.128), ONE fp32 RED.v4 per lane.
__global__ void k_edge(const int* __restrict__ src, const int* __restrict__ dst,
                       const float* __restrict__ w, int E) {
    int tid = blockIdx.x * blockDim.x + threadIdx.x;
    int e = tid >> 4;
    if (e >= E) return;
    int k = tid & 15;
    int s = __ldg(src + e);
    int d = __ldg(dst + e);
    float wv = __ldg(w + e);
    const float4* xt4 = (const float4*)g_xt;
    float4 v = xt4[(size_t)s * 16 + k];
    float4* p = (float4*)g_agg + (size_t)d * 16 + k;
    asm volatile("red.global.add.v4.f32 [%0], {%1, %2, %3, %4};"
                 :: "l"(p), "f"(v.x * wv), "f"(v.y * wv),
                    "f"(v.z * wv), "f"(v.w * wv) : "memory");
}

// ---------------------------------------------------------------------------
// Layer-1 tail + layer-2 HypLinear (K=64). R6/R9-proven geometry.
// 128 thr = 4 warps; 1 pass x 8 nodes per warp = 32 nodes/block, grid 2500.
// Re-zeroes g_agg rows after use. Computes hb2 in-block.
#define L2_UP 8
#define L2_NB 32
__global__ void __launch_bounds__(128)
k_lin2(const float4* __restrict__ W2, const float* __restrict__ b2, int N) {
    __shared__ float4 ws[64 * 17];                       // 17.4 KB padded
    __shared__ __align__(16) float hs[L2_NB][64];        // 8 KB
    __shared__ float hbs[66];

    int tid = threadIdx.x, lane = tid & 31, wib = tid >> 5;

    if (wib == 0) compute_hb(b2, hbs, lane);

    for (int i = tid; i < 1024; i += 128) {
        int j = i >> 4, f = i & 15;
        ws[j * 17 + f] = W2[i];
    }

    int nbase = blockIdx.x * L2_NB + wib * L2_UP;
    float a0[L2_UP], a1[L2_UP];
#pragma unroll
    for (int u = 0; u < L2_UP; u++) {
        int node = nbase + u;
        a0[u] = 0.f; a1[u] = 0.f;
        if (node < N) {
            a0[u] = g_agg[(size_t)node * 64 + lane];
            a1[u] = g_agg[(size_t)node * 64 + lane + 32];
            g_agg[(size_t)node * 64 + lane]      = 0.f;   // re-zero for layer 2
            g_agg[(size_t)node * 64 + lane + 32] = 0.f;
        }
    }
    __syncthreads();                                     // ws + hbs ready

    const float4* wr0 = ws + (size_t)lane * 17;
    const float4* wr1 = ws + (size_t)(lane + 32) * 17;
    float (*hw)[64] = &hs[wib * L2_UP];                  // warp-private

    float h0[L2_UP], h1[L2_UP], xn[L2_UP];
    agg_to_hN<L2_UP>(a0, a1, h0, h1, xn);
#pragma unroll
    for (int u = 0; u < L2_UP; u++) {
        hw[u][lane]      = h0[u];
        hw[u][lane + 32] = h1[u];
    }
    __syncwarp();

    float acc0[L2_UP], acc1[L2_UP];
#pragma unroll
    for (int u = 0; u < L2_UP; u++) { acc0[u] = 0.f; acc1[u] = 0.f; }
#pragma unroll 4
    for (int f = 0; f < 16; f++) {
        float4 wa = wr0[f];
        float4 wb = wr1[f];
#pragma unroll
        for (int u = 0; u < L2_UP; u++) {
            float4 xv = ((const float4*)hw[u])[f];       // broadcast LDS
            acc0[u] += xv.x*wa.x + xv.y*wa.y + xv.z*wa.z + xv.w*wa.w;
            acc1[u] += xv.x*wb.x + xv.y*wb.y + xv.z*wb.z + xv.w*wb.w;
        }
    }
    epilogueN<L2_UP>(acc0, acc1, xn, hbs, lane, nbase, N, g_xt);
}

// ---------------------------------------------------------------------------
// Final: g_agg -> HypAgg/HypAct tail -> d_out. 8 nodes per warp, interleaved.
__global__ void __launch_bounds__(256)
k_final(float* __restrict__ out, int N) {
    int lane = threadIdx.x & 31;
    int wib  = threadIdx.x >> 5;
    int nbase = (blockIdx.x * 8 + wib) * 8;
    if (nbase >= N) return;
    float a0[8], a1[8];
#pragma unroll
    for (int u = 0; u < 8; u++) {
        int node = nbase + u;
        a0[u] = 0.f; a1[u] = 0.f;
        if (node < N) {
            a0[u] = g_agg[(size_t)node * 64 + lane];
            a1[u] = g_agg[(size_t)node * 64 + lane + 32];
        }
    }
    float h0[8], h1[8], xn[8];
    agg_to_hN<8>(a0, a1, h0, h1, xn);
#pragma unroll
    for (int u = 0; u < 8; u++) {
        int node = nbase + u;
        if (node < N) {
            out[(size_t)node * 64 + lane]      = h0[u];
            out[(size_t)node * 64 + lane + 32] = h1[u];
        }
    }
}

// ---------------------------------------------------------------------------
extern "C" void kernel_launch(void* const* d_in, const int* in_sizes, int n_in,
                              void* d_out, int out_size) {
    const float* x  = (const float*)d_in[0];
    const int* src  = (const int*)d_in[1];
    const int* dst  = (const int*)d_in[2];
    const float* ew = (const float*)d_in[3];
    const float* W1 = (const float*)d_in[4];
    const float* b1 = (const float*)d_in[5];
    const float* W2 = (const float*)d_in[6];
    const float* b2 = (const float*)d_in[7];

    int N = in_sizes[0] / 256;
    int E = in_sizes[1];
    if (N > NMAX) N = NMAX;

    int edge_blocks = (int)(((long long)E * 16 + 255) / 256);

    static bool attr_set = false;
    const int l1_smem = (L1_WS + 6 * L1_UP * 64) * 16;   // 91,136 B
    if (!attr_set) {
        cudaFuncSetAttribute(k_lin1, cudaFuncAttributeMaxDynamicSharedMemorySize, l1_smem);
        attr_set = true;
    }

    // Layer 1 (computes hb1 in-block; zeroes g_agg)
    k_lin1<<<(N + L1_NB - 1) / L1_NB, L1_NT, l1_smem>>>(
        (const float4*)x, (const float4*)W1, b1, N);
    k_edge<<<edge_blocks, 256>>>(src, dst, ew, E);

    // Layer 1 tail + layer 2 linear (computes hb2 in-block; re-zeroes g_agg)
    k_lin2<<<(N + L2_NB - 1) / L2_NB, 128>>>((const float4*)W2, b2, N);
    k_edge<<<edge_blocks, 256>>>(src, dst, ew, E);

    // Layer 2 tail -> output
    k_final<<<(N + 63) / 64, 256>>>((float*)d_out, N);
}